// round 16
// baseline (speedup 1.0000x reference)
#include <cuda_runtime.h>
#include <cuda_bf16.h>
#include <mma.h>
#include <cstdint>

using namespace nvcuda;

#define BATCH 2
#define APTS 20000
#define BN 1024
#define NNEI 192
#define GNUM 64

static __device__ float4 g_p4[BATCH*APTS];                 // x,y,z,|x|^2
static __device__ float  g_RtC[BN][12];
static __device__ int    g_gmask[BN];
static __device__ float  g_gpts[BN*GNUM*3];
static __device__ __nv_bfloat16 g_W2tb[512*256];           // k-major [k][o]
static __device__ __nv_bfloat16 g_W3tb[256*256];
static __device__ __nv_bfloat16 g_W4tb[256*128];

// ---------------- merged prep kernel ----------------
#define PREP_PTS (BATCH*APTS)
#define PREP_GR  BN
#define PREP_W   (512*256 + 256*256 + 256*128)
#define PREP_TOT (PREP_PTS + PREP_GR + PREP_W)

__global__ void prep_kernel(const float* __restrict__ pc, const float* __restrict__ grasp,
                            const float* __restrict__ W2, const float* __restrict__ W3,
                            const float* __restrict__ W4) {
  int id = blockIdx.x*blockDim.x + threadIdx.x;
  if (id < PREP_PTS) {
    int i = id;
    float x = pc[i*6+0], y = pc[i*6+1], z = pc[i*6+2];
    float xx = __fadd_rn(__fadd_rn(__fmul_rn(x,x),__fmul_rn(y,y)),__fmul_rn(z,z));
    g_p4[i] = make_float4(x,y,z,xx);
    return;
  }
  if (id < PREP_PTS + PREP_GR) {
    int g = id - PREP_PTS;
    const float* gr = grasp + g*8;
    float s8 = 0.f;
    for (int k=0;k<8;k++) s8 += gr[k];
    g_gmask[g] = (s8 != -8.0f) ? 1 : 0;
    float cx=gr[0], cy=gr[1], cz=gr[2];
    float ay0=gr[3], ay1=gr[4], ay2=gr[5];
    float ang=gr[6];
    float c=cosf(ang), s=sinf(ang);
    float ny = sqrtf(ay0*ay0+ay1*ay1+ay2*ay2);
    ay0 = ay0/(ny+1e-12f); ay1 = ay1/(ny+1e-12f); ay2 = ay2/(ny+1e-12f);
    float ax0=ay1, ax1=-ay0;
    float nx = sqrtf(ax0*ax0+ax1*ax1);
    ax0 = ax0/(nx+1e-12f); ax1 = ax1/(nx+1e-12f);
    float az0 = ax1*ay2;
    float az1 = -ax0*ay2;
    float az2 = ax0*ay1 - ax1*ay0;
    float nz = sqrtf(az0*az0+az1*az1+az2*az2);
    if (nz == 0.0f) { az0=0.f; az1=0.f; az2=1.f; }
    else { az0/=nz; az1/=nz; az2/=nz; }
    float ap0 = c*ax0 + s*az0;
    float ap1 = c*ax1 + s*az1;
    float ap2 = s*az2;
    float na = sqrtf(ap0*ap0+ap1*ap1+ap2*ap2);
    ap0 = ap0/(na+1e-12f); ap1 = ap1/(na+1e-12f); ap2 = ap2/(na+1e-12f);
    float mn0 = ap1*ay2 - ap2*ay1;
    float mn1 = ap2*ay0 - ap0*ay2;
    float mn2 = ap0*ay1 - ap1*ay0;
    float* R = g_RtC[g];
    R[0]=ap0; R[1]=ap1; R[2]=ap2;
    R[3]=ay0; R[4]=ay1; R[5]=ay2;
    R[6]=mn0; R[7]=mn1; R[8]=mn2;
    R[9]=cx;  R[10]=cy; R[11]=cz;
    return;
  }
  int wi = id - (PREP_PTS + PREP_GR);
  if (wi < 512*256) {
    int k = wi >> 8, o = wi & 255;
    g_W2tb[wi] = __float2bfloat16(W2[o*512 + k]);
  } else if (wi < 512*256 + 256*256) {
    int r = wi - 512*256;
    int k = r >> 8, o = r & 255;
    g_W3tb[r] = __float2bfloat16(W3[o*256 + k]);
  } else if (wi < PREP_W) {
    int r = wi - (512*256 + 256*256);
    int k = r >> 7, o = r & 127;
    g_W4tb[r] = __float2bfloat16(W4[o*256 + k]);
  }
}

// ---------------- ball query (round-9 known-good) ----------------

__global__ void __launch_bounds__(256) bq_kernel(const float* __restrict__ grasp,
                                                 float* __restrict__ out) {
  __shared__ int s_list[8][NNEI];
  __shared__ int s_app[8], s_tot[8];
  __shared__ int s_off[8], s_take[8];
  __shared__ int s_run, s_totvalid, s_ccount;
  __shared__ int s_nbr[NNEI];
  __shared__ float s_t[NNEI][3];
  __shared__ unsigned char s_in[NNEI];
  __shared__ int s_sel[GNUM];
  __shared__ float s_R[12];

  int g = blockIdx.x;
  int b = g >> 9;
  int tx = threadIdx.x;
  int w = tx >> 5, lane = tx & 31;
  const float* gr = grasp + g*8;
  float cx=gr[0], cy=gr[1], cz=gr[2];
  float cc = __fadd_rn(__fadd_rn(__fmul_rn(cx,cx),__fmul_rn(cy,cy)),__fmul_rn(cz,cz));
  if (tx < 12) s_R[tx] = g_RtC[g][tx];

  const int chunk = APTS/8;
  int lo = b*APTS + w*chunk, hi = lo + chunk;
  int tot=0, app=0;
  for (int base=lo; base<hi; base+=32) {
    int i = base + lane;
    bool ok=false;
    if (i < hi) {
      float4 p = g_p4[i];
      float dot = __fadd_rn(__fadd_rn(__fmul_rn(cx,p.x),__fmul_rn(cy,p.y)),
                            __fmul_rn(cz,p.z));
      float d2 = __fsub_rn(__fadd_rn(cc, p.w), __fmul_rn(2.0f,dot));
      ok = d2 < 0.09f;
    }
    unsigned mb = __ballot_sync(0xffffffffu, ok);
    if (ok) {
      int pos = app + __popc(mb & ((1u<<lane)-1u));
      if (pos < NNEI) s_list[w][pos] = i - b*APTS;
    }
    tot += __popc(mb);
    app = tot < NNEI ? tot : NNEI;
  }
  if (lane==0) { s_app[w]=app; s_tot[w]=tot; }
  __syncthreads();

  if (tx==0) {
    int run=0, totv=0;
    for (int ww=0; ww<8; ww++) {
      totv += s_tot[ww];
      s_off[ww] = run;
      int t = s_app[ww];
      if (t > NNEI-run) t = NNEI-run;
      if (t < 0) t = 0;
      s_take[ww] = t;
      run += t;
    }
    s_run = run; s_totvalid = totv;
  }
  __syncthreads();
  {
    int take = s_take[w], off = s_off[w];
    for (int j=lane; j<take; j+=32) s_nbr[off+j] = s_list[w][j];
  }
  __syncthreads();
  {
    int run = s_run;
    int pad = (run>0) ? s_nbr[0] : 0;
    for (int j=run+tx; j<NNEI; j+=256) s_nbr[j] = pad;
  }
  __syncthreads();

  for (int p=tx; p<NNEI; p+=blockDim.x) {
    float4 pt = g_p4[b*APTS + s_nbr[p]];
    float vx = pt.x-s_R[9], vy = pt.y-s_R[10], vz = pt.z-s_R[11];
    float t0 = s_R[0]*vx + s_R[1]*vy + s_R[2]*vz;
    float t1 = s_R[3]*vx + s_R[4]*vy + s_R[5]*vz;
    float t2 = s_R[6]*vx + s_R[7]*vy + s_R[8]*vz;
    s_t[p][0]=t0; s_t[p][1]=t1; s_t[p][2]=t2;
    bool ins = (t0>0.0f)&&(t0<0.3f)&&(t1>-0.15f)&&(t1<0.15f)&&(t2>-0.1f)&&(t2<0.1f);
    s_in[p] = ins ? 1 : 0;
  }
  __syncthreads();

  if (tx < 32) {
    int totI=0, first=-1;
    for (int ch=0; ch<NNEI/32; ch++) {
      int p = ch*32 + lane;
      bool ok = s_in[p]!=0;
      unsigned mm = __ballot_sync(0xffffffffu, ok);
      int app64 = totI<GNUM ? totI : GNUM;
      if (ok) {
        int pos = app64 + __popc(mm & ((1u<<lane)-1u));
        if (pos < GNUM) s_sel[pos] = p;
      }
      if (first<0 && mm) first = ch*32 + __ffs(mm)-1;
      totI += __popc(mm);
    }
    int cc64 = totI<GNUM ? totI : GNUM;
    int pad = (totI>0) ? first : 0;
    for (int j=lane; j<GNUM; j+=32) if (j>=cc64) s_sel[j]=pad;
    if (lane==0) s_ccount = cc64;
  }
  __syncthreads();

  for (int idx=tx; idx<GNUM*3; idx+=blockDim.x) {
    int n = idx/3, d = idx - n*3;
    g_gpts[g*(GNUM*3)+idx] = s_t[s_sel[n]][d];
  }
  if (tx==0) {
    bool mk = (s_totvalid>0) && (s_ccount>0) && (g_gmask[g]!=0);
    out[10240 + g] = mk ? 1.0f : 0.0f;
  }
}

// ---------------- fused MLP (layers 1-4) + heads, one block per grasp ----------------
// B operands loaded DIRECTLY from global (L2/L1-resident weights) — no staging, no
// in-loop barriers for layers 3/4.
// smem: LO region [0,10240): h1 chunk [64][72]bf16 | per-warp f32 epilogue scratch
//       [8][320] | head scratch.  s_act [64][264]bf16 (aliased f32 [64][132] out).
#define PAD264 264
#define OPAD 132

__global__ void __launch_bounds__(256) mlp_fused_kernel(
  const float* __restrict__ W1, const float* __restrict__ b1,
  const float* __restrict__ b2, const float* __restrict__ b3, const float* __restrict__ b4,
  const float* __restrict__ stage1,
  const float* __restrict__ reg_w, const float* __restrict__ reg_b,
  const float* __restrict__ cls_w, const float* __restrict__ cls_b,
  const float* __restrict__ dc_reg_w, const float* __restrict__ dc_reg_b,
  const float* __restrict__ dc_cls_w, const float* __restrict__ dc_cls_b,
  float* __restrict__ out)
{
  __shared__ alignas(16) char s_lo[10240];
  __shared__ alignas(16) char s_hi[64*PAD264*2];   // 33792 B
  __shared__ float s_pts[GNUM*3];
  __shared__ float s_bias2[256], s_bias3[256], s_bias4[128];

  __nv_bfloat16* s_h1  = reinterpret_cast<__nv_bfloat16*>(s_lo);   // [64][72]
  float*         s_hd  = reinterpret_cast<float*>(s_lo);            // head scratch
  __nv_bfloat16* s_act = reinterpret_cast<__nv_bfloat16*>(s_hi);   // [64][264]
  float*         s_out = reinterpret_cast<float*>(s_hi);            // [64][132]

  int tx = threadIdx.x;
  int g = blockIdx.x;
  int wid = tx >> 5, lane = tx & 31;
  if (tx < GNUM*3) s_pts[tx] = g_gpts[g*(GNUM*3)+tx];
  if (tx < 128) { s_bias2[tx] = b2[tx]; s_bias2[128+tx] = b2[128+tx];
                  s_bias3[tx] = b3[tx]; s_bias3[128+tx] = b3[128+tx];
                  s_bias4[tx] = b4[tx]; }

  float* wscr = reinterpret_cast<float*>(s_lo) + wid*320;  // per-warp epilogue scratch

  wmma::fragment<wmma::accumulator,16,16,16,float> acc8[8];
  #pragma unroll
  for (int f=0;f<8;f++) wmma::fill_fragment(acc8[f], 0.0f);
  int m0 = (wid & 3) * 16;
  int cIdx = wid >> 2;
  int n0 = cIdx * 128;
  int kl = tx & 63;
  int nb = tx >> 6;
  __syncthreads();

  // ======== layer 1+2: acc = h1 @ W2t  (K=512, N=256), B from global ========
  for (int kt=0; kt<8; kt++) {
    int k = kt*64 + kl;
    float w0=W1[k*3], w1=W1[k*3+1], w2=W1[k*3+2], bb1=b1[k];
    #pragma unroll
    for (int t=0;t<16;t++) {
      int n = nb*16 + t;
      float v = fmaf(w2, s_pts[n*3+2], fmaf(w1, s_pts[n*3+1], fmaf(w0, s_pts[n*3+0], bb1)));
      s_h1[n*72 + kl] = __float2bfloat16(v>0.f ? v : 0.f);
    }
    __syncthreads();
    #pragma unroll
    for (int ks=0; ks<4; ks++) {
      wmma::fragment<wmma::matrix_a,16,16,16,__nv_bfloat16,wmma::row_major> fa;
      wmma::load_matrix_sync(fa, s_h1 + m0*72 + ks*16, 72);
      #pragma unroll
      for (int f=0;f<8;f++) {
        wmma::fragment<wmma::matrix_b,16,16,16,__nv_bfloat16,wmma::row_major> fb;
        wmma::load_matrix_sync(fb, g_W2tb + (kt*64 + ks*16)*256 + n0 + 16*f, 256);
        wmma::mma_sync(acc8[f], fa, fb, acc8[f]);
      }
    }
    __syncthreads();
  }

  // epilogue 2: act = bf16(relu(acc + b2)) — warp-private
  #pragma unroll
  for (int f=0; f<8; f++) {
    wmma::store_matrix_sync(wscr, acc8[f], 20, wmma::mem_row_major);
    __syncwarp();
    #pragma unroll
    for (int j=0;j<8;j++) {
      int e = lane*8 + j;
      int r = e>>4, c = e&15;
      int o = n0 + f*16 + c;
      float v = wscr[r*20+c] + s_bias2[o];
      v = v>0.f ? v : 0.f;
      s_act[(m0+r)*PAD264 + o] = __float2bfloat16(v);
    }
    __syncwarp();
  }
  __syncthreads();

  // ======== layer 3: acc = act @ W3t (K=256, N=256) — NO in-loop barriers ========
  #pragma unroll
  for (int f=0;f<8;f++) wmma::fill_fragment(acc8[f], 0.0f);
  for (int kt=0; kt<16; kt++) {
    wmma::fragment<wmma::matrix_a,16,16,16,__nv_bfloat16,wmma::row_major> fa;
    wmma::load_matrix_sync(fa, s_act + m0*PAD264 + kt*16, PAD264);
    #pragma unroll
    for (int f=0;f<8;f++) {
      wmma::fragment<wmma::matrix_b,16,16,16,__nv_bfloat16,wmma::row_major> fb;
      wmma::load_matrix_sync(fb, g_W3tb + (kt*16)*256 + n0 + 16*f, 256);
      wmma::mma_sync(acc8[f], fa, fb, acc8[f]);
    }
  }
  __syncthreads();   // all warps done READING act before epilogue overwrites

  // epilogue 3: act = bf16(relu(acc + b3)) — in place
  #pragma unroll
  for (int f=0; f<8; f++) {
    wmma::store_matrix_sync(wscr, acc8[f], 20, wmma::mem_row_major);
    __syncwarp();
    #pragma unroll
    for (int j=0;j<8;j++) {
      int e = lane*8 + j;
      int r = e>>4, c = e&15;
      int o = n0 + f*16 + c;
      float v = wscr[r*20+c] + s_bias3[o];
      v = v>0.f ? v : 0.f;
      s_act[(m0+r)*PAD264 + o] = __float2bfloat16(v);
    }
    __syncwarp();
  }
  __syncthreads();

  // ======== layer 4: acc = act @ W4t (K=256, N=128) — NO in-loop barriers ========
  #pragma unroll
  for (int f=0;f<4;f++) wmma::fill_fragment(acc8[f], 0.0f);
  int n40 = cIdx * 64;
  for (int kt=0; kt<16; kt++) {
    wmma::fragment<wmma::matrix_a,16,16,16,__nv_bfloat16,wmma::row_major> fa;
    wmma::load_matrix_sync(fa, s_act + m0*PAD264 + kt*16, PAD264);
    #pragma unroll
    for (int f=0;f<4;f++) {
      wmma::fragment<wmma::matrix_b,16,16,16,__nv_bfloat16,wmma::row_major> fb;
      wmma::load_matrix_sync(fb, g_W4tb + (kt*16)*128 + n40 + 16*f, 128);
      wmma::mma_sync(acc8[f], fa, fb, acc8[f]);
    }
  }
  __syncthreads();   // all warps done reading act before s_out overwrite
  #pragma unroll
  for (int f=0;f<4;f++)
    wmma::store_matrix_sync(s_out + m0*OPAD + n40 + 16*f, acc8[f], OPAD, wmma::mem_row_major);

  // ======== heads ========
  float* s_dc  = s_hd;          // 640
  float* s_rw2 = s_hd + 640;    // 1280
  float* s_pt  = s_hd + 1920;   // 80
  for (int i=tx;i<512;i+=256) s_dc[i]     = dc_reg_w[i];
  for (int i=tx;i<128;i+=256) s_dc[512+i] = dc_cls_w[i];
  for (int i=tx;i<1280;i+=256) {
    int c = i>>7, j = i&127;
    s_rw2[i] = (c<8) ? reg_w[c*384 + 256 + j] : cls_w[(c-8)*384 + 256 + j];
  }
  __syncthreads();

  int hn0 = wid*8, j0 = lane*4;
  float bj[4];
  #pragma unroll
  for (int q=0;q<4;q++) bj[q] = s_bias4[j0+q];
  #pragma unroll
  for (int c=0;c<10;c++) {
    const float* dcw = (c<8) ? (s_dc + c*64) : (s_dc + 512 + (c-8)*64);
    const float* rw2 = s_rw2 + c*128 + j0;
    float pc_ = 0.f;
    #pragma unroll
    for (int i=0;i<8;i++) {
      float t = 0.f;
      #pragma unroll
      for (int q=0;q<4;q++) {
        float h = s_out[(hn0+i)*OPAD + j0+q] + bj[q];
        h = h>0.f ? h : 0.f;
        t = fmaf(rw2[q], h, t);
      }
      pc_ = fmaf(dcw[hn0+i], t, pc_);
    }
    #pragma unroll
    for (int off=16; off>0; off>>=1) pc_ += __shfl_down_sync(0xffffffffu, pc_, off);
    if (lane==0) s_pt[c*8 + wid] = pc_;
  }
  __syncthreads();

  for (int c = wid; c < 10; c += 8) {
    float hd = (lane < 8) ? s_pt[c*8 + lane] : 0.f;
    const float* rw = (c<8) ? (reg_w + c*384) : (cls_w + (c-8)*384);
    const float* s1 = stage1 + g*256;
    float s1d = 0.f;
    #pragma unroll
    for (int t=0;t<8;t++) {
      int j = lane + 32*t;
      s1d = fmaf(rw[j], s1[j], s1d);
    }
    const float* dcw = (c<8) ? (s_dc + c*64) : (s_dc + 512 + (c-8)*64);
    float S = dcw[lane] + dcw[lane+32];
    #pragma unroll
    for (int off=16; off>0; off>>=1) {
      hd  += __shfl_down_sync(0xffffffffu, hd,  off);
      s1d += __shfl_down_sync(0xffffffffu, s1d, off);
      S   += __shfl_down_sync(0xffffffffu, S,   off);
    }
    if (lane==0) {
      float bc  = (c<8) ? reg_b[c] : cls_b[c-8];
      float dcb = (c<8) ? dc_reg_b[c] : dc_cls_b[c-8];
      float o = hd + (s1d + bc)*S + dcb;
      if (c < 8) out[2048 + g*8 + c] = o;
      else       out[g*2 + (c-8)]   = o;
    }
  }
}

// ---------------- launch ----------------

extern "C" void kernel_launch(void* const* d_in, const int* in_sizes, int n_in,
                              void* d_out, int out_size) {
  const float* grasp  = (const float*)d_in[0];
  const float* pc     = (const float*)d_in[1];
  const float* stage1 = (const float*)d_in[3];
  const float* W1 = (const float*)d_in[4];  const float* b1 = (const float*)d_in[5];
  const float* W2 = (const float*)d_in[6];  const float* b2 = (const float*)d_in[7];
  const float* W3 = (const float*)d_in[8];  const float* b3 = (const float*)d_in[9];
  const float* W4 = (const float*)d_in[10]; const float* b4 = (const float*)d_in[11];
  const float* reg_w = (const float*)d_in[12]; const float* reg_b = (const float*)d_in[13];
  const float* cls_w = (const float*)d_in[14]; const float* cls_b = (const float*)d_in[15];
  const float* dcrw  = (const float*)d_in[16]; const float* dcrb  = (const float*)d_in[17];
  const float* dccw  = (const float*)d_in[18]; const float* dccb  = (const float*)d_in[19];
  float* out = (float*)d_out;

  prep_kernel<<<(PREP_TOT + 255)/256, 256>>>(pc, grasp, W2, W3, W4);
  bq_kernel<<<BN, 256>>>(grasp, out);
  mlp_fused_kernel<<<BN, 256>>>(W1, b1, b2, b3, b4, stage1,
                                reg_w, reg_b, cls_w, cls_b,
                                dcrw, dcrb, dccw, dccb, out);
}

// round 17
// speedup vs baseline: 2.4979x; 2.4979x over previous
#include <cuda_runtime.h>
#include <cuda_bf16.h>
#include <mma.h>
#include <cstdint>

using namespace nvcuda;

#define BATCH 2
#define APTS 20000
#define BN 1024
#define NNEI 192
#define GNUM 64

static __device__ float4 g_p4[BATCH*APTS];                 // x,y,z,|x|^2
static __device__ float  g_RtC[BN][12];
static __device__ int    g_gmask[BN];
static __device__ float  g_gpts[BN*GNUM*3];
static __device__ __nv_bfloat16 g_W2tb[512*256];           // k-major [k][o]
static __device__ __nv_bfloat16 g_W3tb[256*256];
static __device__ __nv_bfloat16 g_W4tb[256*128];

// ---------------- merged prep kernel ----------------
#define PREP_PTS (BATCH*APTS)
#define PREP_GR  BN
#define PREP_W   (512*256 + 256*256 + 256*128)
#define PREP_TOT (PREP_PTS + PREP_GR + PREP_W)

__global__ void prep_kernel(const float* __restrict__ pc, const float* __restrict__ grasp,
                            const float* __restrict__ W2, const float* __restrict__ W3,
                            const float* __restrict__ W4) {
  int id = blockIdx.x*blockDim.x + threadIdx.x;
  if (id < PREP_PTS) {
    int i = id;
    float x = pc[i*6+0], y = pc[i*6+1], z = pc[i*6+2];
    float xx = __fadd_rn(__fadd_rn(__fmul_rn(x,x),__fmul_rn(y,y)),__fmul_rn(z,z));
    g_p4[i] = make_float4(x,y,z,xx);
    return;
  }
  if (id < PREP_PTS + PREP_GR) {
    int g = id - PREP_PTS;
    const float* gr = grasp + g*8;
    float s8 = 0.f;
    for (int k=0;k<8;k++) s8 += gr[k];
    g_gmask[g] = (s8 != -8.0f) ? 1 : 0;
    float cx=gr[0], cy=gr[1], cz=gr[2];
    float ay0=gr[3], ay1=gr[4], ay2=gr[5];
    float ang=gr[6];
    float c=cosf(ang), s=sinf(ang);
    float ny = sqrtf(ay0*ay0+ay1*ay1+ay2*ay2);
    ay0 = ay0/(ny+1e-12f); ay1 = ay1/(ny+1e-12f); ay2 = ay2/(ny+1e-12f);
    float ax0=ay1, ax1=-ay0;
    float nx = sqrtf(ax0*ax0+ax1*ax1);
    ax0 = ax0/(nx+1e-12f); ax1 = ax1/(nx+1e-12f);
    float az0 = ax1*ay2;
    float az1 = -ax0*ay2;
    float az2 = ax0*ay1 - ax1*ay0;
    float nz = sqrtf(az0*az0+az1*az1+az2*az2);
    if (nz == 0.0f) { az0=0.f; az1=0.f; az2=1.f; }
    else { az0/=nz; az1/=nz; az2/=nz; }
    float ap0 = c*ax0 + s*az0;
    float ap1 = c*ax1 + s*az1;
    float ap2 = s*az2;
    float na = sqrtf(ap0*ap0+ap1*ap1+ap2*ap2);
    ap0 = ap0/(na+1e-12f); ap1 = ap1/(na+1e-12f); ap2 = ap2/(na+1e-12f);
    float mn0 = ap1*ay2 - ap2*ay1;
    float mn1 = ap2*ay0 - ap0*ay2;
    float mn2 = ap0*ay1 - ap1*ay0;
    float* R = g_RtC[g];
    R[0]=ap0; R[1]=ap1; R[2]=ap2;
    R[3]=ay0; R[4]=ay1; R[5]=ay2;
    R[6]=mn0; R[7]=mn1; R[8]=mn2;
    R[9]=cx;  R[10]=cy; R[11]=cz;
    return;
  }
  int wi = id - (PREP_PTS + PREP_GR);
  if (wi < 512*256) {
    int k = wi >> 8, o = wi & 255;
    g_W2tb[wi] = __float2bfloat16(W2[o*512 + k]);
  } else if (wi < 512*256 + 256*256) {
    int r = wi - 512*256;
    int k = r >> 8, o = r & 255;
    g_W3tb[r] = __float2bfloat16(W3[o*256 + k]);
  } else if (wi < PREP_W) {
    int r = wi - (512*256 + 256*256);
    int k = r >> 7, o = r & 127;
    g_W4tb[r] = __float2bfloat16(W4[o*256 + k]);
  }
}

// ---------------- ball query (round-9 known-good) ----------------

__global__ void __launch_bounds__(256) bq_kernel(const float* __restrict__ grasp,
                                                 float* __restrict__ out) {
  __shared__ int s_list[8][NNEI];
  __shared__ int s_app[8], s_tot[8];
  __shared__ int s_off[8], s_take[8];
  __shared__ int s_run, s_totvalid, s_ccount;
  __shared__ int s_nbr[NNEI];
  __shared__ float s_t[NNEI][3];
  __shared__ unsigned char s_in[NNEI];
  __shared__ int s_sel[GNUM];
  __shared__ float s_R[12];

  int g = blockIdx.x;
  int b = g >> 9;
  int tx = threadIdx.x;
  int w = tx >> 5, lane = tx & 31;
  const float* gr = grasp + g*8;
  float cx=gr[0], cy=gr[1], cz=gr[2];
  float cc = __fadd_rn(__fadd_rn(__fmul_rn(cx,cx),__fmul_rn(cy,cy)),__fmul_rn(cz,cz));
  if (tx < 12) s_R[tx] = g_RtC[g][tx];

  const int chunk = APTS/8;
  int lo = b*APTS + w*chunk, hi = lo + chunk;
  int tot=0, app=0;
  for (int base=lo; base<hi; base+=32) {
    int i = base + lane;
    bool ok=false;
    if (i < hi) {
      float4 p = g_p4[i];
      float dot = __fadd_rn(__fadd_rn(__fmul_rn(cx,p.x),__fmul_rn(cy,p.y)),
                            __fmul_rn(cz,p.z));
      float d2 = __fsub_rn(__fadd_rn(cc, p.w), __fmul_rn(2.0f,dot));
      ok = d2 < 0.09f;
    }
    unsigned mb = __ballot_sync(0xffffffffu, ok);
    if (ok) {
      int pos = app + __popc(mb & ((1u<<lane)-1u));
      if (pos < NNEI) s_list[w][pos] = i - b*APTS;
    }
    tot += __popc(mb);
    app = tot < NNEI ? tot : NNEI;
  }
  if (lane==0) { s_app[w]=app; s_tot[w]=tot; }
  __syncthreads();

  if (tx==0) {
    int run=0, totv=0;
    for (int ww=0; ww<8; ww++) {
      totv += s_tot[ww];
      s_off[ww] = run;
      int t = s_app[ww];
      if (t > NNEI-run) t = NNEI-run;
      if (t < 0) t = 0;
      s_take[ww] = t;
      run += t;
    }
    s_run = run; s_totvalid = totv;
  }
  __syncthreads();
  {
    int take = s_take[w], off = s_off[w];
    for (int j=lane; j<take; j+=32) s_nbr[off+j] = s_list[w][j];
  }
  __syncthreads();
  {
    int run = s_run;
    int pad = (run>0) ? s_nbr[0] : 0;
    for (int j=run+tx; j<NNEI; j+=256) s_nbr[j] = pad;
  }
  __syncthreads();

  for (int p=tx; p<NNEI; p+=blockDim.x) {
    float4 pt = g_p4[b*APTS + s_nbr[p]];
    float vx = pt.x-s_R[9], vy = pt.y-s_R[10], vz = pt.z-s_R[11];
    float t0 = s_R[0]*vx + s_R[1]*vy + s_R[2]*vz;
    float t1 = s_R[3]*vx + s_R[4]*vy + s_R[5]*vz;
    float t2 = s_R[6]*vx + s_R[7]*vy + s_R[8]*vz;
    s_t[p][0]=t0; s_t[p][1]=t1; s_t[p][2]=t2;
    bool ins = (t0>0.0f)&&(t0<0.3f)&&(t1>-0.15f)&&(t1<0.15f)&&(t2>-0.1f)&&(t2<0.1f);
    s_in[p] = ins ? 1 : 0;
  }
  __syncthreads();

  if (tx < 32) {
    int totI=0, first=-1;
    for (int ch=0; ch<NNEI/32; ch++) {
      int p = ch*32 + lane;
      bool ok = s_in[p]!=0;
      unsigned mm = __ballot_sync(0xffffffffu, ok);
      int app64 = totI<GNUM ? totI : GNUM;
      if (ok) {
        int pos = app64 + __popc(mm & ((1u<<lane)-1u));
        if (pos < GNUM) s_sel[pos] = p;
      }
      if (first<0 && mm) first = ch*32 + __ffs(mm)-1;
      totI += __popc(mm);
    }
    int cc64 = totI<GNUM ? totI : GNUM;
    int pad = (totI>0) ? first : 0;
    for (int j=lane; j<GNUM; j+=32) if (j>=cc64) s_sel[j]=pad;
    if (lane==0) s_ccount = cc64;
  }
  __syncthreads();

  for (int idx=tx; idx<GNUM*3; idx+=blockDim.x) {
    int n = idx/3, d = idx - n*3;
    g_gpts[g*(GNUM*3)+idx] = s_t[s_sel[n]][d];
  }
  if (tx==0) {
    bool mk = (s_totvalid>0) && (s_ccount>0) && (g_gmask[g]!=0);
    out[10240 + g] = mk ? 1.0f : 0.0f;
  }
}

// ---------------- fused MLP (layers 1-4) + heads, one block per grasp ----------------
// Round-9 chassis (sync uint4 staging, no occ cap) + 2m x 4n warp tiling:
// warp = (mg = wid&1 -> m0 = mg*32, 2 A-frags) x (ng = wid>>1 -> n0 = ng*64, 4 B-frags).
// Halves B-fragment LDSM duplication (4x -> 2x).
// smem union (44032 B):
//   LO [0,10240):  h1 [64][72]bf16 | B3 [16][264]bf16 | B4 [32][136]bf16
//                  | per-warp f32 epilogue scratch [8][320] | head scratch
//   HI [10240,44032): B2 [64][264]bf16 | act [64][264]bf16 | out f32 [64][132]
#define PAD264 264
#define OPAD 132

__global__ void __launch_bounds__(256) mlp_fused_kernel(
  const float* __restrict__ W1, const float* __restrict__ b1,
  const float* __restrict__ b2, const float* __restrict__ b3, const float* __restrict__ b4,
  const float* __restrict__ stage1,
  const float* __restrict__ reg_w, const float* __restrict__ reg_b,
  const float* __restrict__ cls_w, const float* __restrict__ cls_b,
  const float* __restrict__ dc_reg_w, const float* __restrict__ dc_reg_b,
  const float* __restrict__ dc_cls_w, const float* __restrict__ dc_cls_b,
  float* __restrict__ out)
{
  __shared__ alignas(16) char s_u[44032];
  __shared__ float s_pts[GNUM*3];
  __shared__ float s_bias2[256], s_bias3[256], s_bias4[128];

  __nv_bfloat16* s_h1  = reinterpret_cast<__nv_bfloat16*>(s_u);            // [64][72]
  __nv_bfloat16* s_b3t = reinterpret_cast<__nv_bfloat16*>(s_u);            // [16][264]
  __nv_bfloat16* s_b4t = reinterpret_cast<__nv_bfloat16*>(s_u);            // [32][136]
  float*         s_hd  = reinterpret_cast<float*>(s_u);                     // head scratch
  __nv_bfloat16* s_b2t = reinterpret_cast<__nv_bfloat16*>(s_u + 10240);    // [64][264]
  __nv_bfloat16* s_act = reinterpret_cast<__nv_bfloat16*>(s_u + 10240);    // [64][264]
  float*         s_out = reinterpret_cast<float*>(s_u + 10240);            // [64][132]

  int tx = threadIdx.x;
  int g = blockIdx.x;
  int wid = tx >> 5, lane = tx & 31;
  if (tx < GNUM*3) s_pts[tx] = g_gpts[g*(GNUM*3)+tx];
  if (tx < 128) { s_bias2[tx] = b2[tx]; s_bias2[128+tx] = b2[128+tx];
                  s_bias3[tx] = b3[tx]; s_bias3[128+tx] = b3[128+tx];
                  s_bias4[tx] = b4[tx]; }

  float* wscr = reinterpret_cast<float*>(s_u) + wid*320;   // per-warp epilogue scratch

  // warp tiling: 2 m-groups x 4 n-groups
  int m0 = (wid & 1) * 32;      // 2 A-frags: m0, m0+16
  int n0 = (wid >> 1) * 64;     // 4 B-frags: n0 + 16f

  wmma::fragment<wmma::accumulator,16,16,16,float> acc[2][4];
  #pragma unroll
  for (int mi=0;mi<2;mi++)
    #pragma unroll
    for (int f=0;f<4;f++) wmma::fill_fragment(acc[mi][f], 0.0f);

  int kl = tx & 63;
  int nb = tx >> 6;
  __syncthreads();

  // ======== layer 1+2: acc = h1 @ W2t  (K=512, N=256) ========
  for (int kt=0; kt<8; kt++) {
    // stage B2 tile [64][256] (sync uint4)
    #pragma unroll
    for (int t=0;t<8;t++) {
      int idx = tx + 256*t;
      int r = idx >> 5, c8 = idx & 31;
      reinterpret_cast<uint4*>(s_b2t + r*PAD264)[c8] =
        reinterpret_cast<const uint4*>(g_W2tb + (kt*64 + r)*256)[c8];
    }
    // compute h1 tile [64][64]
    int k = kt*64 + kl;
    float w0=W1[k*3], w1=W1[k*3+1], w2=W1[k*3+2], bb1=b1[k];
    #pragma unroll
    for (int t=0;t<16;t++) {
      int n = nb*16 + t;
      float v = fmaf(w2, s_pts[n*3+2], fmaf(w1, s_pts[n*3+1], fmaf(w0, s_pts[n*3+0], bb1)));
      s_h1[n*72 + kl] = __float2bfloat16(v>0.f ? v : 0.f);
    }
    __syncthreads();
    #pragma unroll
    for (int ks=0; ks<4; ks++) {
      wmma::fragment<wmma::matrix_a,16,16,16,__nv_bfloat16,wmma::row_major> fa[2];
      #pragma unroll
      for (int mi=0;mi<2;mi++)
        wmma::load_matrix_sync(fa[mi], s_h1 + (m0+16*mi)*72 + ks*16, 72);
      #pragma unroll
      for (int f=0;f<4;f++) {
        wmma::fragment<wmma::matrix_b,16,16,16,__nv_bfloat16,wmma::row_major> fb;
        wmma::load_matrix_sync(fb, s_b2t + (ks*16)*PAD264 + n0 + 16*f, PAD264);
        #pragma unroll
        for (int mi=0;mi<2;mi++) wmma::mma_sync(acc[mi][f], fa[mi], fb, acc[mi][f]);
      }
    }
    __syncthreads();
  }

  // epilogue 2: act = bf16(relu(acc + b2)) — warp-private
  #pragma unroll
  for (int mi=0; mi<2; mi++) {
    #pragma unroll
    for (int f=0; f<4; f++) {
      wmma::store_matrix_sync(wscr, acc[mi][f], 20, wmma::mem_row_major);
      __syncwarp();
      #pragma unroll
      for (int j=0;j<8;j++) {
        int e = lane*8 + j;
        int r = e>>4, c = e&15;
        int o = n0 + f*16 + c;
        float v = wscr[r*20+c] + s_bias2[o];
        v = v>0.f ? v : 0.f;
        s_act[(m0+16*mi+r)*PAD264 + o] = __float2bfloat16(v);
      }
      __syncwarp();
    }
  }
  __syncthreads();

  // ======== layer 3: acc = act @ W3t  (K=256, N=256), B chunk 16 ========
  #pragma unroll
  for (int mi=0;mi<2;mi++)
    #pragma unroll
    for (int f=0;f<4;f++) wmma::fill_fragment(acc[mi][f], 0.0f);
  for (int kt=0; kt<16; kt++) {
    #pragma unroll
    for (int t=0;t<2;t++) {
      int idx = tx + 256*t;
      int r = idx >> 5, c8 = idx & 31;
      reinterpret_cast<uint4*>(s_b3t + r*PAD264)[c8] =
        reinterpret_cast<const uint4*>(g_W3tb + (kt*16 + r)*256)[c8];
    }
    __syncthreads();
    {
      wmma::fragment<wmma::matrix_a,16,16,16,__nv_bfloat16,wmma::row_major> fa[2];
      #pragma unroll
      for (int mi=0;mi<2;mi++)
        wmma::load_matrix_sync(fa[mi], s_act + (m0+16*mi)*PAD264 + kt*16, PAD264);
      #pragma unroll
      for (int f=0;f<4;f++) {
        wmma::fragment<wmma::matrix_b,16,16,16,__nv_bfloat16,wmma::row_major> fb;
        wmma::load_matrix_sync(fb, s_b3t + n0 + 16*f, PAD264);
        #pragma unroll
        for (int mi=0;mi<2;mi++) wmma::mma_sync(acc[mi][f], fa[mi], fb, acc[mi][f]);
      }
    }
    __syncthreads();
  }

  // epilogue 3: act = bf16(relu(acc + b3)) — in place
  #pragma unroll
  for (int mi=0; mi<2; mi++) {
    #pragma unroll
    for (int f=0; f<4; f++) {
      wmma::store_matrix_sync(wscr, acc[mi][f], 20, wmma::mem_row_major);
      __syncwarp();
      #pragma unroll
      for (int j=0;j<8;j++) {
        int e = lane*8 + j;
        int r = e>>4, c = e&15;
        int o = n0 + f*16 + c;
        float v = wscr[r*20+c] + s_bias3[o];
        v = v>0.f ? v : 0.f;
        s_act[(m0+16*mi+r)*PAD264 + o] = __float2bfloat16(v);
      }
      __syncwarp();
    }
  }
  __syncthreads();

  // ======== layer 4: acc = act @ W4t  (K=256, N=128), B chunk 32 ========
  int n40 = (wid >> 1) * 32;    // 2 B-frags per warp
  wmma::fragment<wmma::accumulator,16,16,16,float> acc4[2][2];
  #pragma unroll
  for (int mi=0;mi<2;mi++)
    #pragma unroll
    for (int f=0;f<2;f++) wmma::fill_fragment(acc4[mi][f], 0.0f);
  for (int kt=0; kt<8; kt++) {
    #pragma unroll
    for (int t=0;t<2;t++) {
      int idx = tx + 256*t;
      int r = idx >> 4, c8 = idx & 15;
      reinterpret_cast<uint4*>(s_b4t + r*136)[c8] =
        reinterpret_cast<const uint4*>(g_W4tb + (kt*32 + r)*128)[c8];
    }
    __syncthreads();
    #pragma unroll
    for (int ks=0; ks<2; ks++) {
      wmma::fragment<wmma::matrix_a,16,16,16,__nv_bfloat16,wmma::row_major> fa[2];
      #pragma unroll
      for (int mi=0;mi<2;mi++)
        wmma::load_matrix_sync(fa[mi], s_act + (m0+16*mi)*PAD264 + kt*32 + ks*16, PAD264);
      #pragma unroll
      for (int f=0;f<2;f++) {
        wmma::fragment<wmma::matrix_b,16,16,16,__nv_bfloat16,wmma::row_major> fb;
        wmma::load_matrix_sync(fb, s_b4t + (ks*16)*136 + n40 + 16*f, 136);
        #pragma unroll
        for (int mi=0;mi<2;mi++) wmma::mma_sync(acc4[mi][f], fa[mi], fb, acc4[mi][f]);
      }
    }
    __syncthreads();
  }
  #pragma unroll
  for (int mi=0;mi<2;mi++)
    #pragma unroll
    for (int f=0;f<2;f++)
      wmma::store_matrix_sync(s_out + (m0+16*mi)*OPAD + n40 + 16*f, acc4[mi][f],
                              OPAD, wmma::mem_row_major);

  // ======== heads ========
  float* s_dc  = s_hd;          // 640
  float* s_rw2 = s_hd + 640;    // 1280
  float* s_pt  = s_hd + 1920;   // 80
  for (int i=tx;i<512;i+=256) s_dc[i]     = dc_reg_w[i];
  for (int i=tx;i<128;i+=256) s_dc[512+i] = dc_cls_w[i];
  for (int i=tx;i<1280;i+=256) {
    int c = i>>7, j = i&127;
    s_rw2[i] = (c<8) ? reg_w[c*384 + 256 + j] : cls_w[(c-8)*384 + 256 + j];
  }
  __syncthreads();

  int hn0 = wid*8, j0 = lane*4;
  float bj[4];
  #pragma unroll
  for (int q=0;q<4;q++) bj[q] = s_bias4[j0+q];
  #pragma unroll
  for (int c=0;c<10;c++) {
    const float* dcw = (c<8) ? (s_dc + c*64) : (s_dc + 512 + (c-8)*64);
    const float* rw2 = s_rw2 + c*128 + j0;
    float pc_ = 0.f;
    #pragma unroll
    for (int i=0;i<8;i++) {
      float t = 0.f;
      #pragma unroll
      for (int q=0;q<4;q++) {
        float h = s_out[(hn0+i)*OPAD + j0+q] + bj[q];
        h = h>0.f ? h : 0.f;
        t = fmaf(rw2[q], h, t);
      }
      pc_ = fmaf(dcw[hn0+i], t, pc_);
    }
    #pragma unroll
    for (int off=16; off>0; off>>=1) pc_ += __shfl_down_sync(0xffffffffu, pc_, off);
    if (lane==0) s_pt[c*8 + wid] = pc_;
  }
  __syncthreads();

  for (int c = wid; c < 10; c += 8) {
    float hd = (lane < 8) ? s_pt[c*8 + lane] : 0.f;
    const float* rw = (c<8) ? (reg_w + c*384) : (cls_w + (c-8)*384);
    const float* s1 = stage1 + g*256;
    float s1d = 0.f;
    #pragma unroll
    for (int t=0;t<8;t++) {
      int j = lane + 32*t;
      s1d = fmaf(rw[j], s1[j], s1d);
    }
    const float* dcw = (c<8) ? (s_dc + c*64) : (s_dc + 512 + (c-8)*64);
    float S = dcw[lane] + dcw[lane+32];
    #pragma unroll
    for (int off=16; off>0; off>>=1) {
      hd  += __shfl_down_sync(0xffffffffu, hd,  off);
      s1d += __shfl_down_sync(0xffffffffu, s1d, off);
      S   += __shfl_down_sync(0xffffffffu, S,   off);
    }
    if (lane==0) {
      float bc  = (c<8) ? reg_b[c] : cls_b[c-8];
      float dcb = (c<8) ? dc_reg_b[c] : dc_cls_b[c-8];
      float o = hd + (s1d + bc)*S + dcb;
      if (c < 8) out[2048 + g*8 + c] = o;
      else       out[g*2 + (c-8)]   = o;
    }
  }
}

// ---------------- launch ----------------

extern "C" void kernel_launch(void* const* d_in, const int* in_sizes, int n_in,
                              void* d_out, int out_size) {
  const float* grasp  = (const float*)d_in[0];
  const float* pc     = (const float*)d_in[1];
  const float* stage1 = (const float*)d_in[3];
  const float* W1 = (const float*)d_in[4];  const float* b1 = (const float*)d_in[5];
  const float* W2 = (const float*)d_in[6];  const float* b2 = (const float*)d_in[7];
  const float* W3 = (const float*)d_in[8];  const float* b3 = (const float*)d_in[9];
  const float* W4 = (const float*)d_in[10]; const float* b4 = (const float*)d_in[11];
  const float* reg_w = (const float*)d_in[12]; const float* reg_b = (const float*)d_in[13];
  const float* cls_w = (const float*)d_in[14]; const float* cls_b = (const float*)d_in[15];
  const float* dcrw  = (const float*)d_in[16]; const float* dcrb  = (const float*)d_in[17];
  const float* dccw  = (const float*)d_in[18]; const float* dccb  = (const float*)d_in[19];
  float* out = (float*)d_out;

  prep_kernel<<<(PREP_TOT + 255)/256, 256>>>(pc, grasp, W2, W3, W4);
  bq_kernel<<<BN, 256>>>(grasp, out);
  mlp_fused_kernel<<<BN, 256>>>(W1, b1, b2, b3, b4, stage1,
                                reg_w, reg_b, cls_w, cls_b,
                                dcrw, dcrb, dccw, dccb, out);
}